// round 3
// baseline (speedup 1.0000x reference)
#include <cuda_runtime.h>
#include <cuda_bf16.h>

#define BN    32
#define LN    36864
#define CN    16
#define KN    24
#define LOUT  1536
#define DN    512
#define CKN   384          // C*K
#define TM    64           // lout rows per CTA
#define KC    8            // k-chunk for GEMM B staging
#define NSTEP (CKN / KC)   // 48
#define NTHR  256
#define VSTRIDE 68         // padded row stride for s_val (mult of 4, not mult of 32)

// smem layout (floats):
//  s_val [CKN][VSTRIDE] = 26112   (aliases s_xt [CN][TM*KN] = 24576 : phase-disjoint)
//  s_off [TM*48]        = 3072
//  s_b   [2][KC][DN]    = 8192
#define SM_VAL 0
#define SM_OFF 26112
#define SM_B   (SM_OFF + TM * 48)
#define SM_TOT (SM_B + 2 * KC * DN)      // 37376 floats = 149504 B

typedef unsigned long long u64;

__device__ __forceinline__ u64 pack_dup(float a) {
    u64 r; asm("mov.b64 %0, {%1, %2};" : "=l"(r) : "f"(a), "f"(a)); return r;
}
__device__ __forceinline__ void fma2(u64& d, u64 a, u64 b) {
    asm("fma.rn.f32x2 %0, %1, %2, %3;" : "=l"(d) : "l"(a), "l"(b), "l"(d));
}
__device__ __forceinline__ void lds_v2(u64& a, u64& b, const float* p) {
    unsigned addr = (unsigned)__cvta_generic_to_shared(p);
    asm volatile("ld.shared.v2.b64 {%0, %1}, [%2];" : "=l"(a), "=l"(b) : "r"(addr));
}
__device__ __forceinline__ void ldg_v2(u64& a, u64& b, const float* p) {
    asm volatile("ld.global.nc.v2.b64 {%0, %1}, [%2];" : "=l"(a), "=l"(b) : "l"(p));
}
__device__ __forceinline__ void unpack2(float& lo, float& hi, u64 v) {
    asm("mov.b64 {%0, %1}, %2;" : "=f"(lo), "=f"(hi) : "l"(v));
}

__global__ __launch_bounds__(NTHR, 1)
void deform_fused_kernel(const float* __restrict__ x,
                         const float* __restrict__ w_off,
                         const float* __restrict__ b_off,
                         const float* __restrict__ w_def,
                         const float* __restrict__ b_def,
                         float* __restrict__ out)
{
    extern __shared__ float smem[];
    float* s_val = smem + SM_VAL;     // phase 3/4
    float* s_xt  = smem + SM_VAL;     // phase 1/2 (aliased)
    float* s_off = smem + SM_OFF;
    float* s_b   = smem + SM_B;

    const int t    = threadIdx.x;
    const int warp = t >> 5;
    const int lane = t & 31;
    const int g = blockIdx.x;
    const int b = g / (LOUT / TM);
    const int lout0 = (g % (LOUT / TM)) * TM;

    const float* xb = x + (size_t)b * LN * CN;
    const int base_i = lout0 * KN;    // window start row in L

    // ---------------- Phase 1: load x window, store transposed [c][i] -----------
    {
        const float4* xw4 = (const float4*)(xb + (size_t)base_i * CN);
        #pragma unroll
        for (int it = 0; it < (TM * KN * CN / 4) / NTHR; it++) {   // 24
            int idx = t + it * NTHR;
            float4 v = __ldg(&xw4[idx]);
            int i  = idx >> 2;                 // 0..1535
            int c4 = (idx & 3) * 4;
            s_xt[(c4 + 0) * (TM * KN) + i] = v.x;
            s_xt[(c4 + 1) * (TM * KN) + i] = v.y;
            s_xt[(c4 + 2) * (TM * KN) + i] = v.z;
            s_xt[(c4 + 3) * (TM * KN) + i] = v.w;
        }
    }
    __syncthreads();

    // ---------------- Phase 2: offset conv (packed f32x2) -----------------------
    #pragma unroll
    for (int it = 0; it < (TM * 48) / NTHR; it++) {   // 12
        int j = t + it * NTHR;
        int m = j / 48;
        int o = j % 48;
        const float* xrow = s_xt + m * KN;
        const float* wrow = w_off + o * CKN;
        u64 accP = 0ULL, accQ = 0ULL;
        #pragma unroll
        for (int c = 0; c < CN; c++) {
            const float* xc = xrow + c * (TM * KN);
            const float* wc = wrow + c * KN;
            #pragma unroll
            for (int q = 0; q < KN / 4; q++) {          // 6 x (4 floats)
                u64 x0, x1, w0, w1;
                lds_v2(x0, x1, xc + q * 4);
                ldg_v2(w0, w1, wc + q * 4);
                fma2(accP, x0, w0);
                fma2(accQ, x1, w1);
            }
        }
        float p0, p1, q0, q1;
        unpack2(p0, p1, accP);
        unpack2(q0, q1, accQ);
        s_off[j] = __ldg(&b_off[o]) + ((p0 + q0) + (p1 + q1));
    }
    __syncthreads();

    // ---------------- Phase 3: bilinear sampling -> s_val[ck][m] ----------------
    #pragma unroll
    for (int it = 0; it < (TM * KN) / NTHR; it++) {   // 6
        int j = t + it * NTHR;
        int m = j / KN;
        int k = j % KN;
        float dy = s_off[m * 48 + 2 * k];
        float dx = s_off[m * 48 + 2 * k + 1];
        float wy = fmaxf(0.0f, 1.0f - fabsf(dy));
        int lout = lout0 + m;
        float px = (float)(lout * KN + k) + dx;
        bool valid = (px > -1.0f) && (px < (float)LN);
        float x0f = floorf(px);
        float lw = px - x0f;
        int i0 = (int)x0f;
        int i1 = i0 + 1;
        float w0 = (valid && i0 >= 0 && i0 < LN) ? (1.0f - lw) * wy : 0.0f;
        float w1 = (valid && i1 >= 0 && i1 < LN) ? lw * wy : 0.0f;
        int i0c = min(max(i0, 0), LN - 1);
        int i1c = min(max(i1, 0), LN - 1);
        const float4* p0 = (const float4*)(xb + (size_t)i0c * CN);
        const float4* p1 = (const float4*)(xb + (size_t)i1c * CN);
        #pragma unroll
        for (int q = 0; q < 4; q++) {
            float4 v0 = __ldg(&p0[q]);
            float4 v1 = __ldg(&p1[q]);
            int c = q * 4;
            s_val[((c + 0) * KN + k) * VSTRIDE + m] = v0.x * w0 + v1.x * w1;
            s_val[((c + 1) * KN + k) * VSTRIDE + m] = v0.y * w0 + v1.y * w1;
            s_val[((c + 2) * KN + k) * VSTRIDE + m] = v0.z * w0 + v1.z * w1;
            s_val[((c + 3) * KN + k) * VSTRIDE + m] = v0.w * w0 + v1.w * w1;
        }
    }

    // Prefetch w_def chunk 0 and stage into buffer 0 (s_b doesn't alias s_val).
    float4 pf0, pf1, pf2, pf3;
    {
        const float4* wd0 = (const float4*)(w_def + (size_t)t * CKN);
        const float4* wd1 = (const float4*)(w_def + (size_t)(t + 256) * CKN);
        pf0 = __ldg(&wd0[0]); pf1 = __ldg(&wd0[1]);
        pf2 = __ldg(&wd1[0]); pf3 = __ldg(&wd1[1]);
    }
    {
        float* bb = s_b;
        bb[0 * DN + t] = pf0.x; bb[1 * DN + t] = pf0.y;
        bb[2 * DN + t] = pf0.z; bb[3 * DN + t] = pf0.w;
        bb[4 * DN + t] = pf1.x; bb[5 * DN + t] = pf1.y;
        bb[6 * DN + t] = pf1.z; bb[7 * DN + t] = pf1.w;
        int d1 = t + 256;
        bb[0 * DN + d1] = pf2.x; bb[1 * DN + d1] = pf2.y;
        bb[2 * DN + d1] = pf2.z; bb[3 * DN + d1] = pf2.w;
        bb[4 * DN + d1] = pf3.x; bb[5 * DN + d1] = pf3.y;
        bb[6 * DN + d1] = pf3.z; bb[7 * DN + d1] = pf3.w;
    }
    __syncthreads();

    // ---------------- Phase 4: GEMM 64x512x384 with f32x2 FMA -------------------
    // warp w owns rows r0..r0+7 (broadcast a); lane owns cols lane*4 + f*128, f=0..3
    const int r0 = warp * 8;
    const int cb = lane * 4;

    u64 acc[8][8];     // [row][colpair]  (8 rows x 16 cols)
    #pragma unroll
    for (int i = 0; i < 8; i++)
        #pragma unroll
        for (int jj = 0; jj < 8; jj++) acc[i][jj] = 0ULL;

    for (int s = 0; s < NSTEP; s++) {
        if (s + 1 < NSTEP) {
            const float4* wd0 = (const float4*)(w_def + (size_t)t * CKN + (s + 1) * KC);
            const float4* wd1 = (const float4*)(w_def + (size_t)(t + 256) * CKN + (s + 1) * KC);
            pf0 = __ldg(&wd0[0]); pf1 = __ldg(&wd0[1]);
            pf2 = __ldg(&wd1[0]); pf3 = __ldg(&wd1[1]);
        }
        const float* bb = s_b + (s & 1) * (KC * DN);
        #pragma unroll
        for (int kk = 0; kk < KC; kk++) {
            const float* arow = s_val + (s * KC + kk) * VSTRIDE + r0;
            float4 a0 = *(const float4*)(arow);
            float4 a1 = *(const float4*)(arow + 4);
            u64 ad[8];
            ad[0] = pack_dup(a0.x); ad[1] = pack_dup(a0.y);
            ad[2] = pack_dup(a0.z); ad[3] = pack_dup(a0.w);
            ad[4] = pack_dup(a1.x); ad[5] = pack_dup(a1.y);
            ad[6] = pack_dup(a1.z); ad[7] = pack_dup(a1.w);
            const float* brow = bb + kk * DN + cb;
            u64 bp[8];
            lds_v2(bp[0], bp[1], brow + 0 * 128);
            lds_v2(bp[2], bp[3], brow + 1 * 128);
            lds_v2(bp[4], bp[5], brow + 2 * 128);
            lds_v2(bp[6], bp[7], brow + 3 * 128);
            #pragma unroll
            for (int i = 0; i < 8; i++)
                #pragma unroll
                for (int jj = 0; jj < 8; jj++)
                    fma2(acc[i][jj], ad[i], bp[jj]);
        }
        if (s + 1 < NSTEP) {
            float* nb = s_b + ((s + 1) & 1) * (KC * DN);
            nb[0 * DN + t] = pf0.x; nb[1 * DN + t] = pf0.y;
            nb[2 * DN + t] = pf0.z; nb[3 * DN + t] = pf0.w;
            nb[4 * DN + t] = pf1.x; nb[5 * DN + t] = pf1.y;
            nb[6 * DN + t] = pf1.z; nb[7 * DN + t] = pf1.w;
            int d1 = t + 256;
            nb[0 * DN + d1] = pf2.x; nb[1 * DN + d1] = pf2.y;
            nb[2 * DN + d1] = pf2.z; nb[3 * DN + d1] = pf2.w;
            nb[4 * DN + d1] = pf3.x; nb[5 * DN + d1] = pf3.y;
            nb[6 * DN + d1] = pf3.z; nb[7 * DN + d1] = pf3.w;
            __syncthreads();
        }
    }

    // ---------------- Epilogue: bias + store ------------------------------------
    float4 bias[4];
    #pragma unroll
    for (int f = 0; f < 4; f++)
        bias[f] = __ldg((const float4*)(b_def + f * 128 + cb));

    #pragma unroll
    for (int i = 0; i < 8; i++) {
        size_t row = (size_t)b * LOUT + (lout0 + r0 + i);
        float* orow = out + row * DN;
        #pragma unroll
        for (int f = 0; f < 4; f++) {
            float lo0, hi0, lo1, hi1;
            unpack2(lo0, hi0, acc[i][2 * f]);
            unpack2(lo1, hi1, acc[i][2 * f + 1]);
            float4 o;
            o.x = lo0 + bias[f].x;
            o.y = hi0 + bias[f].y;
            o.z = lo1 + bias[f].z;
            o.w = hi1 + bias[f].w;
            *(float4*)(orow + f * 128 + cb) = o;
        }
    }
}

extern "C" void kernel_launch(void* const* d_in, const int* in_sizes, int n_in,
                              void* d_out, int out_size)
{
    const float* x     = (const float*)d_in[0];
    const float* w_off = (const float*)d_in[1];
    const float* b_off = (const float*)d_in[2];
    const float* w_def = (const float*)d_in[3];
    const float* b_def = (const float*)d_in[4];
    float* out = (float*)d_out;

    const int smem_bytes = SM_TOT * (int)sizeof(float);   // 149504 B
    static bool attr_set = false;
    if (!attr_set) {
        cudaFuncSetAttribute(deform_fused_kernel,
                             cudaFuncAttributeMaxDynamicSharedMemorySize, smem_bytes);
        attr_set = true;
    }

    dim3 grid(BN * (LOUT / TM));   // 768 CTAs
    dim3 block(NTHR);
    deform_fused_kernel<<<grid, block, smem_bytes>>>(x, w_off, b_off, w_def, b_def, out);
}

// round 9
// speedup vs baseline: 2.1282x; 2.1282x over previous
#include <cuda_runtime.h>
#include <cuda_bf16.h>
#include <cstdint>

#define BN    32
#define LN    36864
#define CN    16
#define KN    24
#define LOUT  1536
#define DN    512
#define CKN   384
#define MTOT  (BN * LOUT)      // 49152

// single TU-wide dynamic smem symbol
extern __shared__ char smem_c[];

// ---------------- global scratch (bf16 split: hi | lo) ----------------------
__device__ __nv_bfloat16 g_A[(size_t)MTOT * 768];   // [m][0:384 hi | 384:768 lo]
__device__ __nv_bfloat16 g_B[(size_t)DN * 768];     // [d][0:384 hi | 384:768 lo]

// ---------------- PTX helpers ------------------------------------------------
typedef unsigned long long u64;

__device__ __forceinline__ void fma2(u64& d, u64 a, u64 b) {
    asm("fma.rn.f32x2 %0, %1, %2, %3;" : "=l"(d) : "l"(a), "l"(b), "l"(d));
}
__device__ __forceinline__ void lds_v2(u64& a, u64& b, const float* p) {
    unsigned addr = (unsigned)__cvta_generic_to_shared(p);
    asm volatile("ld.shared.v2.b64 {%0, %1}, [%2];" : "=l"(a), "=l"(b) : "r"(addr));
}
__device__ __forceinline__ void ldg_v2(u64& a, u64& b, const float* p) {
    asm volatile("ld.global.nc.v2.b64 {%0, %1}, [%2];" : "=l"(a), "=l"(b) : "l"(p));
}
__device__ __forceinline__ void unpack2(float& lo, float& hi, u64 v) {
    asm("mov.b64 {%0, %1}, %2;" : "=f"(lo), "=f"(hi) : "l"(v));
}
__device__ __forceinline__ uint32_t smem_u32(const void* p) {
    return (uint32_t)__cvta_generic_to_shared(p);
}

#define SWZ128(off) ((off) ^ (((off) >> 3) & 0x70))

__device__ __forceinline__ void cp_async16(uint32_t saddr, const void* gptr) {
    asm volatile("cp.async.cg.shared.global [%0], [%1], 16;" :: "r"(saddr), "l"(gptr));
}
#define CP_COMMIT() asm volatile("cp.async.commit_group;" ::: "memory")
#define CP_WAIT(N)  asm volatile("cp.async.wait_group %0;" :: "n"(N) : "memory")

__device__ __forceinline__ void ldm_x4(uint32_t& r0, uint32_t& r1, uint32_t& r2,
                                       uint32_t& r3, uint32_t addr) {
    asm volatile("ldmatrix.sync.aligned.m8n8.x4.shared.b16 {%0,%1,%2,%3}, [%4];"
                 : "=r"(r0), "=r"(r1), "=r"(r2), "=r"(r3) : "r"(addr));
}
__device__ __forceinline__ void mma_bf16(float* d, const uint32_t* a, const uint32_t* b) {
    asm volatile(
        "mma.sync.aligned.m16n8k16.row.col.f32.bf16.bf16.f32 "
        "{%0,%1,%2,%3}, {%4,%5,%6,%7}, {%8,%9}, {%0,%1,%2,%3};"
        : "+f"(d[0]), "+f"(d[1]), "+f"(d[2]), "+f"(d[3])
        : "r"(a[0]), "r"(a[1]), "r"(a[2]), "r"(a[3]), "r"(b[0]), "r"(b[1]));
}

// =============================================================================
// Kernel A: split w_def -> g_B (hi | lo)
// =============================================================================
__global__ void split_wdef_kernel(const float* __restrict__ w_def) {
    int idx = blockIdx.x * blockDim.x + threadIdx.x;
    if (idx >= DN * CKN) return;
    int row = idx / CKN, col = idx % CKN;
    float v = __ldg(&w_def[idx]);
    __nv_bfloat16 hi = __float2bfloat16_rn(v);
    __nv_bfloat16 lo = __float2bfloat16_rn(v - __bfloat162float(hi));
    g_B[(size_t)row * 768 + col] = hi;
    g_B[(size_t)row * 768 + 384 + col] = lo;
}

// =============================================================================
// Kernel B: producer — offsets + bilinear sampling -> g_A (hi | lo)
// =============================================================================
#define TM1    32
#define NTHR1  256
#define VST    388

#define SM1_OFF 12416
#define SM1_TOT (SM1_OFF + TM1 * 48)     // 13952 floats = 55808 B

__global__ __launch_bounds__(NTHR1, 1)
void producer_kernel(const float* __restrict__ x,
                     const float* __restrict__ w_off,
                     const float* __restrict__ b_off)
{
    float* smem  = (float*)smem_c;
    float* s_xt  = smem;
    float* s_val = smem;            // aliased; phases disjoint
    float* s_off = smem + SM1_OFF;

    const int t    = threadIdx.x;
    const int warp = t >> 5;
    const int lane = t & 31;
    const int g = blockIdx.x;
    const int b = g / (LOUT / TM1);
    const int lout0 = (g % (LOUT / TM1)) * TM1;

    const float* xb = x + (size_t)b * LN * CN;
    const int base_i = lout0 * KN;

    // Phase 1: stage x window transposed [c][i]
    {
        const float4* xw4 = (const float4*)(xb + (size_t)base_i * CN);
        #pragma unroll
        for (int it = 0; it < (TM1 * KN * CN / 4) / NTHR1; it++) {   // 12
            int idx = t + it * NTHR1;
            float4 v = __ldg(&xw4[idx]);
            int i  = idx >> 2;
            int c4 = (idx & 3) * 4;
            s_xt[(c4 + 0) * (TM1 * KN) + i] = v.x;
            s_xt[(c4 + 1) * (TM1 * KN) + i] = v.y;
            s_xt[(c4 + 2) * (TM1 * KN) + i] = v.z;
            s_xt[(c4 + 3) * (TM1 * KN) + i] = v.w;
        }
    }
    __syncthreads();

    // Phase 2: offset conv (f32x2)
    #pragma unroll
    for (int it = 0; it < (TM1 * 48) / NTHR1; it++) {                // 6
        int j = t + it * NTHR1;
        int m = j / 48;
        int o = j % 48;
        const float* xrow = s_xt + m * KN;
        const float* wrow = w_off + o * CKN;
        u64 accP = 0ULL, accQ = 0ULL;
        #pragma unroll
        for (int c = 0; c < CN; c++) {
            const float* xc = xrow + c * (TM1 * KN);
            const float* wc = wrow + c * KN;
            #pragma unroll
            for (int q = 0; q < KN / 4; q++) {
                u64 x0, x1, w0, w1;
                lds_v2(x0, x1, xc + q * 4);
                ldg_v2(w0, w1, wc + q * 4);
                fma2(accP, x0, w0);
                fma2(accQ, x1, w1);
            }
        }
        float p0, p1, q0, q1;
        unpack2(p0, p1, accP);
        unpack2(q0, q1, accQ);
        s_off[j] = __ldg(&b_off[o]) + ((p0 + q0) + (p1 + q1));
    }
    __syncthreads();

    // Phase 3: bilinear sampling -> s_val[m][ck]
    #pragma unroll
    for (int it = 0; it < (TM1 * KN) / NTHR1; it++) {                // 3
        int j = t + it * NTHR1;
        int m = j / KN;
        int k = j % KN;
        float dy = s_off[m * 48 + 2 * k];
        float dx = s_off[m * 48 + 2 * k + 1];
        float wy = fmaxf(0.0f, 1.0f - fabsf(dy));
        int lout = lout0 + m;
        float px = (float)(lout * KN + k) + dx;
        bool valid = (px > -1.0f) && (px < (float)LN);
        float x0f = floorf(px);
        float lw = px - x0f;
        int i0 = (int)x0f;
        int i1 = i0 + 1;
        float w0 = (valid && i0 >= 0 && i0 < LN) ? (1.0f - lw) * wy : 0.0f;
        float w1 = (valid && i1 >= 0 && i1 < LN) ? lw * wy : 0.0f;
        int i0c = min(max(i0, 0), LN - 1);
        int i1c = min(max(i1, 0), LN - 1);
        const float4* p0 = (const float4*)(xb + (size_t)i0c * CN);
        const float4* p1 = (const float4*)(xb + (size_t)i1c * CN);
        float* vrow = s_val + m * VST + k;
        #pragma unroll
        for (int q = 0; q < 4; q++) {
            float4 v0 = __ldg(&p0[q]);
            float4 v1 = __ldg(&p1[q]);
            int c = q * 4;
            vrow[(c + 0) * KN] = v0.x * w0 + v1.x * w1;
            vrow[(c + 1) * KN] = v0.y * w0 + v1.y * w1;
            vrow[(c + 2) * KN] = v0.z * w0 + v1.z * w1;
            vrow[(c + 3) * KN] = v0.w * w0 + v1.w * w1;
        }
    }
    __syncthreads();

    // Phase 4: convert to bf16 hi/lo, coalesced store to g_A
    uint32_t* gA32 = (uint32_t*)g_A;
    #pragma unroll
    for (int it = 0; it < TM1 / 8; it++) {                           // 4
        int m = warp + 8 * it;
        size_t m_glob = (size_t)b * LOUT + lout0 + m;
        uint32_t* rowp = gA32 + m_glob * 384;
        const float* vrow = s_val + m * VST;
        #pragma unroll
        for (int q = 0; q < 6; q++) {
            int c2 = lane + 32 * q;
            float v0 = vrow[2 * c2];
            float v1 = vrow[2 * c2 + 1];
            __nv_bfloat162 h2, l2;
            h2.x = __float2bfloat16_rn(v0);
            h2.y = __float2bfloat16_rn(v1);
            l2.x = __float2bfloat16_rn(v0 - __bfloat162float(h2.x));
            l2.y = __float2bfloat16_rn(v1 - __bfloat162float(h2.y));
            rowp[c2]       = *(uint32_t*)&h2;
            rowp[192 + c2] = *(uint32_t*)&l2;
        }
    }
}

// =============================================================================
// Kernel C: mma.sync bf16 GEMM  out[49152][512] = g_A x g_B^T (3-term split)
// CTA 128x128, 8 warps (2x4), warp tile 64x32, k-chunk 64, 2-stage cp.async.
// =============================================================================
#define NTHR2 256
#define NCHUNK 18

// smem byte layout: A[2][16384] B[2][16384]
#define SM2A0 0
#define SM2B0 16384
#define SM2A1 32768
#define SM2B1 49152
#define SM2_TOT 65536

__global__ __launch_bounds__(NTHR2, 2)
void gemm_mma_kernel(const float* __restrict__ b_def, float* __restrict__ out)
{
    const uint32_t sb = smem_u32(smem_c);
    const int t    = threadIdx.x;
    const int wid  = t >> 5;
    const int lane = t & 31;
    const int m0g  = blockIdx.x * 128;
    const int n0g  = blockIdx.y * 128;

    const int wm = (wid >> 2) * 64;     // warp m-offset in CTA tile
    const int wn = (wid & 3) * 32;      // warp n-offset

    // per-thread cp.async source/dst precompute: 4 A rows + 4 B rows (16B each)
    const int prow = t >> 3;            // 0..31 (x4 iterations -> 128 rows)
    const int pc16 = t & 7;             // 16B column within 128B row

    float acc[4][4][4];
    #pragma unroll
    for (int i = 0; i < 4; i++)
        #pragma unroll
        for (int j = 0; j < 4; j++)
            #pragma unroll
            for (int e = 0; e < 4; e++) acc[i][j][e] = 0.0f;

    auto prefetch = [&](int c) {
        int buf = c & 1;
        int seg = c / 6, r = c % 6;
        int aOff = (seg == 1 ? 384 : 0) + 64 * r;
        int bOff = (seg == 2 ? 384 : 0) + 64 * r;
        uint32_t sA = sb + (buf ? SM2A1 : SM2A0);
        uint32_t sB = sb + (buf ? SM2B1 : SM2B0);
        #pragma unroll
        for (int i = 0; i < 4; i++) {
            int row = prow + i * 32;
            cp_async16(sA + SWZ128(row * 128 + pc16 * 16),
                       g_A + (size_t)(m0g + row) * 768 + aOff + pc16 * 8);
        }
        #pragma unroll
        for (int i = 0; i < 4; i++) {
            int row = prow + i * 32;
            cp_async16(sB + SWZ128(row * 128 + pc16 * 16),
                       g_B + (size_t)(n0g + row) * 768 + bOff + pc16 * 8);
        }
    };

    prefetch(0);
    CP_COMMIT();

    for (int c = 0; c < NCHUNK; c++) {
        if (c + 1 < NCHUNK) {
            prefetch(c + 1);
            CP_COMMIT();
            CP_WAIT(1);
        } else {
            CP_WAIT(0);
        }
        __syncthreads();

        int buf = c & 1;
        uint32_t sA = sb + (buf ? SM2A1 : SM2A0);
        uint32_t sB = sb + (buf ? SM2B1 : SM2B0);

        #pragma unroll
        for (int k16 = 0; k16 < 4; k16++) {
            int kb = k16 * 32;
            // A frags: 4 x m16 tiles
            uint32_t a[4][4];
            #pragma unroll
            for (int i = 0; i < 4; i++) {
                int row  = wm + i * 16 + (lane & 15);
                int colb = kb + ((lane & 16) ? 16 : 0);
                ldm_x4(a[i][0], a[i][1], a[i][2], a[i][3],
                       sA + SWZ128(row * 128 + colb));
            }
            // B frags: 4 x n8 tiles via 2 ldmatrix.x4
            uint32_t bf[4][2];
            #pragma unroll
            for (int p = 0; p < 2; p++) {
                int grp  = lane >> 3;                  // 0..3
                int nt   = p * 2 + (grp >> 1);         // n8 tile index
                int half = grp & 1;                    // k half
                int row  = wn + nt * 8 + (lane & 7);
                int colb = kb + half * 16;
                uint32_t r0, r1, r2, r3;
                ldm_x4(r0, r1, r2, r3, sB + SWZ128(row * 128 + colb));
                bf[p * 2][0] = r0;  bf[p * 2][1] = r1;
                bf[p * 2 + 1][0] = r2;  bf[p * 2 + 1][1] = r3;
            }
            #pragma unroll
            for (int i = 0; i < 4; i++)
                #pragma unroll
                for (int j = 0; j < 4; j++)
                    mma_bf16(acc[i][j], a[i], bf[j]);
        }
        __syncthreads();
    }

    // epilogue: add bias, store float2 per (row, n-pair)
    #pragma unroll
    for (int j = 0; j < 4; j++) {
        int n = n0g + wn + j * 8 + (lane & 3) * 2;
        float2 bias = __ldg((const float2*)(b_def + n));
        #pragma unroll
        for (int i = 0; i < 4; i++) {
            int m = m0g + wm + i * 16 + (lane >> 2);
            float2 v0 = make_float2(acc[i][j][0] + bias.x, acc[i][j][1] + bias.y);
            float2 v1 = make_float2(acc[i][j][2] + bias.x, acc[i][j][3] + bias.y);
            *(float2*)(out + (size_t)m * DN + n) = v0;
            *(float2*)(out + (size_t)(m + 8) * DN + n) = v1;
        }
    }
}

// =============================================================================
extern "C" void kernel_launch(void* const* d_in, const int* in_sizes, int n_in,
                              void* d_out, int out_size)
{
    const float* x     = (const float*)d_in[0];
    const float* w_off = (const float*)d_in[1];
    const float* b_off = (const float*)d_in[2];
    const float* w_def = (const float*)d_in[3];
    const float* b_def = (const float*)d_in[4];
    float* out = (float*)d_out;

    static bool attr_set = false;
    if (!attr_set) {
        cudaFuncSetAttribute(producer_kernel,
                             cudaFuncAttributeMaxDynamicSharedMemorySize,
                             SM1_TOT * (int)sizeof(float));
        cudaFuncSetAttribute(gemm_mma_kernel,
                             cudaFuncAttributeMaxDynamicSharedMemorySize, SM2_TOT);
        attr_set = true;
    }

    split_wdef_kernel<<<(DN * CKN + 255) / 256, 256>>>(w_def);
    producer_kernel<<<BN * (LOUT / TM1), NTHR1, SM1_TOT * sizeof(float)>>>(x, w_off, b_off);
    dim3 grid2(MTOT / 128, DN / 128);     // 384 x 4
    gemm_mma_kernel<<<grid2, NTHR2, SM2_TOT>>>(b_def, out);
}

// round 10
// speedup vs baseline: 2.3425x; 1.1007x over previous
#include <cuda_runtime.h>
#include <cuda_bf16.h>
#include <cuda_fp16.h>
#include <cstdint>

#define BN    32
#define LN    36864
#define CN    16
#define KN    24
#define LOUT  1536
#define DN    512
#define CKN   384
#define MTOT  (BN * LOUT)      // 49152

// single TU-wide dynamic smem symbol
extern __shared__ char smem_c[];

// ---------------- global scratch (fp16) --------------------------------------
__device__ __half g_A[(size_t)MTOT * 384];   // [m][384]  single fp16
__device__ __half g_B[(size_t)DN * 768];     // [d][0:384 hi | 384:768 lo]

// ---------------- PTX helpers ------------------------------------------------
typedef unsigned long long u64;

__device__ __forceinline__ void fma2(u64& d, u64 a, u64 b) {
    asm("fma.rn.f32x2 %0, %1, %2, %3;" : "=l"(d) : "l"(a), "l"(b), "l"(d));
}
__device__ __forceinline__ void lds_v2(u64& a, u64& b, const float* p) {
    unsigned addr = (unsigned)__cvta_generic_to_shared(p);
    asm volatile("ld.shared.v2.b64 {%0, %1}, [%2];" : "=l"(a), "=l"(b) : "r"(addr));
}
__device__ __forceinline__ void ldg_v2(u64& a, u64& b, const float* p) {
    asm volatile("ld.global.nc.v2.b64 {%0, %1}, [%2];" : "=l"(a), "=l"(b) : "l"(p));
}
__device__ __forceinline__ void unpack2(float& lo, float& hi, u64 v) {
    asm("mov.b64 {%0, %1}, %2;" : "=f"(lo), "=f"(hi) : "l"(v));
}
__device__ __forceinline__ uint32_t smem_u32(const void* p) {
    return (uint32_t)__cvta_generic_to_shared(p);
}

#define SWZ128(off) ((off) ^ (((off) >> 3) & 0x70))

__device__ __forceinline__ void cp_async16(uint32_t saddr, const void* gptr) {
    asm volatile("cp.async.cg.shared.global [%0], [%1], 16;" :: "r"(saddr), "l"(gptr));
}
#define CP_COMMIT() asm volatile("cp.async.commit_group;" ::: "memory")
#define CP_WAIT(N)  asm volatile("cp.async.wait_group %0;" :: "n"(N) : "memory")

__device__ __forceinline__ void ldm_x4(uint32_t& r0, uint32_t& r1, uint32_t& r2,
                                       uint32_t& r3, uint32_t addr) {
    asm volatile("ldmatrix.sync.aligned.m8n8.x4.shared.b16 {%0,%1,%2,%3}, [%4];"
                 : "=r"(r0), "=r"(r1), "=r"(r2), "=r"(r3) : "r"(addr));
}
__device__ __forceinline__ void mma_fp16(float* d, const uint32_t* a, const uint32_t* b) {
    asm volatile(
        "mma.sync.aligned.m16n8k16.row.col.f32.f16.f16.f32 "
        "{%0,%1,%2,%3}, {%4,%5,%6,%7}, {%8,%9}, {%0,%1,%2,%3};"
        : "+f"(d[0]), "+f"(d[1]), "+f"(d[2]), "+f"(d[3])
        : "r"(a[0]), "r"(a[1]), "r"(a[2]), "r"(a[3]), "r"(b[0]), "r"(b[1]));
}

// =============================================================================
// Kernel A: split w_def -> g_B (fp16 hi | lo)
// =============================================================================
__global__ void split_wdef_kernel(const float* __restrict__ w_def) {
    int idx = blockIdx.x * blockDim.x + threadIdx.x;
    if (idx >= DN * CKN) return;
    int row = idx / CKN, col = idx % CKN;
    float v = __ldg(&w_def[idx]);
    __half hi = __float2half_rn(v);
    __half lo = __float2half_rn(v - __half2float(hi));
    g_B[(size_t)row * 768 + col] = hi;
    g_B[(size_t)row * 768 + 384 + col] = lo;
}

// =============================================================================
// Kernel B: producer — offsets + bilinear sampling -> g_A (fp16)
// =============================================================================
#define TM1    32
#define NTHR1  256
#define VST    388

#define SM1_OFF 12416
#define SM1_TOT (SM1_OFF + TM1 * 48)     // 13952 floats = 55808 B

__global__ __launch_bounds__(NTHR1, 1)
void producer_kernel(const float* __restrict__ x,
                     const float* __restrict__ w_off,
                     const float* __restrict__ b_off)
{
    float* smem  = (float*)smem_c;
    float* s_xt  = smem;
    float* s_val = smem;            // aliased; phases disjoint
    float* s_off = smem + SM1_OFF;

    const int t    = threadIdx.x;
    const int warp = t >> 5;
    const int lane = t & 31;
    const int g = blockIdx.x;
    const int b = g / (LOUT / TM1);
    const int lout0 = (g % (LOUT / TM1)) * TM1;

    const float* xb = x + (size_t)b * LN * CN;
    const int base_i = lout0 * KN;

    // Phase 1: stage x window transposed [c][i]
    {
        const float4* xw4 = (const float4*)(xb + (size_t)base_i * CN);
        #pragma unroll
        for (int it = 0; it < (TM1 * KN * CN / 4) / NTHR1; it++) {   // 12
            int idx = t + it * NTHR1;
            float4 v = __ldg(&xw4[idx]);
            int i  = idx >> 2;
            int c4 = (idx & 3) * 4;
            s_xt[(c4 + 0) * (TM1 * KN) + i] = v.x;
            s_xt[(c4 + 1) * (TM1 * KN) + i] = v.y;
            s_xt[(c4 + 2) * (TM1 * KN) + i] = v.z;
            s_xt[(c4 + 3) * (TM1 * KN) + i] = v.w;
        }
    }
    __syncthreads();

    // Phase 2: offset conv (f32x2)
    #pragma unroll
    for (int it = 0; it < (TM1 * 48) / NTHR1; it++) {                // 6
        int j = t + it * NTHR1;
        int m = j / 48;
        int o = j % 48;
        const float* xrow = s_xt + m * KN;
        const float* wrow = w_off + o * CKN;
        u64 accP = 0ULL, accQ = 0ULL;
        #pragma unroll
        for (int c = 0; c < CN; c++) {
            const float* xc = xrow + c * (TM1 * KN);
            const float* wc = wrow + c * KN;
            #pragma unroll
            for (int q = 0; q < KN / 4; q++) {
                u64 x0, x1, w0, w1;
                lds_v2(x0, x1, xc + q * 4);
                ldg_v2(w0, w1, wc + q * 4);
                fma2(accP, x0, w0);
                fma2(accQ, x1, w1);
            }
        }
        float p0, p1, q0, q1;
        unpack2(p0, p1, accP);
        unpack2(q0, q1, accQ);
        s_off[j] = __ldg(&b_off[o]) + ((p0 + q0) + (p1 + q1));
    }
    __syncthreads();

    // Phase 3: bilinear sampling -> s_val[m][ck]
    #pragma unroll
    for (int it = 0; it < (TM1 * KN) / NTHR1; it++) {                // 3
        int j = t + it * NTHR1;
        int m = j / KN;
        int k = j % KN;
        float dy = s_off[m * 48 + 2 * k];
        float dx = s_off[m * 48 + 2 * k + 1];
        float wy = fmaxf(0.0f, 1.0f - fabsf(dy));
        int lout = lout0 + m;
        float px = (float)(lout * KN + k) + dx;
        bool valid = (px > -1.0f) && (px < (float)LN);
        float x0f = floorf(px);
        float lw = px - x0f;
        int i0 = (int)x0f;
        int i1 = i0 + 1;
        float w0 = (valid && i0 >= 0 && i0 < LN) ? (1.0f - lw) * wy : 0.0f;
        float w1 = (valid && i1 >= 0 && i1 < LN) ? lw * wy : 0.0f;
        int i0c = min(max(i0, 0), LN - 1);
        int i1c = min(max(i1, 0), LN - 1);
        const float4* p0 = (const float4*)(xb + (size_t)i0c * CN);
        const float4* p1 = (const float4*)(xb + (size_t)i1c * CN);
        float* vrow = s_val + m * VST + k;
        #pragma unroll
        for (int q = 0; q < 4; q++) {
            float4 v0 = __ldg(&p0[q]);
            float4 v1 = __ldg(&p1[q]);
            int c = q * 4;
            vrow[(c + 0) * KN] = v0.x * w0 + v1.x * w1;
            vrow[(c + 1) * KN] = v0.y * w0 + v1.y * w1;
            vrow[(c + 2) * KN] = v0.z * w0 + v1.z * w1;
            vrow[(c + 3) * KN] = v0.w * w0 + v1.w * w1;
        }
    }
    __syncthreads();

    // Phase 4: convert to fp16, coalesced store to g_A
    uint32_t* gA32 = (uint32_t*)g_A;
    #pragma unroll
    for (int it = 0; it < TM1 / 8; it++) {                           // 4
        int m = warp + 8 * it;
        size_t m_glob = (size_t)b * LOUT + lout0 + m;
        uint32_t* rowp = gA32 + m_glob * 192;       // 384 fp16 = 192 u32
        const float* vrow = s_val + m * VST;
        #pragma unroll
        for (int q = 0; q < 6; q++) {
            int c2 = lane + 32 * q;                 // u32 index 0..191
            __half2 h2 = __floats2half2_rn(vrow[2 * c2], vrow[2 * c2 + 1]);
            rowp[c2] = *(uint32_t*)&h2;
        }
    }
}

// =============================================================================
// Kernel C: mma.sync fp16 GEMM  out[49152][512] = g_A x (B_hi + B_lo)^T
// CTA 128x128, 8 warps (2x4), warp tile 64x32, k-chunk 64, 2-stage cp.async.
// 12 chunks: pass 0 = A x B_hi (6), pass 1 = A x B_lo (6).
// =============================================================================
#define NTHR2 256
#define NCHUNK 12

// smem byte layout: A[2][16384] B[2][16384]
#define SM2A0 0
#define SM2B0 16384
#define SM2A1 32768
#define SM2B1 49152
#define SM2_TOT 65536

__global__ __launch_bounds__(NTHR2, 2)
void gemm_mma_kernel(const float* __restrict__ b_def, float* __restrict__ out)
{
    const uint32_t sb = smem_u32(smem_c);
    const int t    = threadIdx.x;
    const int wid  = t >> 5;
    const int lane = t & 31;
    const int m0g  = blockIdx.x * 128;
    const int n0g  = blockIdx.y * 128;

    const int wm = (wid >> 2) * 64;     // warp m-offset in CTA tile
    const int wn = (wid & 3) * 32;      // warp n-offset

    const int prow = t >> 3;            // 0..31 (x4 iterations -> 128 rows)
    const int pc16 = t & 7;             // 16B column within 128B row

    float acc[4][4][4];
    #pragma unroll
    for (int i = 0; i < 4; i++)
        #pragma unroll
        for (int j = 0; j < 4; j++)
            #pragma unroll
            for (int e = 0; e < 4; e++) acc[i][j][e] = 0.0f;

    auto prefetch = [&](int c) {
        int buf = c & 1;
        int r = c % 6;
        int aOff = 64 * r;                       // A: single 384-col row
        int bOff = (c / 6) * 384 + 64 * r;       // B: hi then lo
        uint32_t sA = sb + (buf ? SM2A1 : SM2A0);
        uint32_t sB = sb + (buf ? SM2B1 : SM2B0);
        #pragma unroll
        for (int i = 0; i < 4; i++) {
            int row = prow + i * 32;
            cp_async16(sA + SWZ128(row * 128 + pc16 * 16),
                       g_A + (size_t)(m0g + row) * 384 + aOff + pc16 * 8);
        }
        #pragma unroll
        for (int i = 0; i < 4; i++) {
            int row = prow + i * 32;
            cp_async16(sB + SWZ128(row * 128 + pc16 * 16),
                       g_B + (size_t)(n0g + row) * 768 + bOff + pc16 * 8);
        }
    };

    prefetch(0);
    CP_COMMIT();

    for (int c = 0; c < NCHUNK; c++) {
        if (c + 1 < NCHUNK) {
            prefetch(c + 1);
            CP_COMMIT();
            CP_WAIT(1);
        } else {
            CP_WAIT(0);
        }
        __syncthreads();

        int buf = c & 1;
        uint32_t sA = sb + (buf ? SM2A1 : SM2A0);
        uint32_t sB = sb + (buf ? SM2B1 : SM2B0);

        #pragma unroll
        for (int k16 = 0; k16 < 4; k16++) {
            int kb = k16 * 32;
            uint32_t a[4][4];
            #pragma unroll
            for (int i = 0; i < 4; i++) {
                int row  = wm + i * 16 + (lane & 15);
                int colb = kb + ((lane & 16) ? 16 : 0);
                ldm_x4(a[i][0], a[i][1], a[i][2], a[i][3],
                       sA + SWZ128(row * 128 + colb));
            }
            uint32_t bf[4][2];
            #pragma unroll
            for (int p = 0; p < 2; p++) {
                int grp  = lane >> 3;
                int nt   = p * 2 + (grp >> 1);
                int half = grp & 1;
                int row  = wn + nt * 8 + (lane & 7);
                int colb = kb + half * 16;
                uint32_t r0, r1, r2, r3;
                ldm_x4(r0, r1, r2, r3, sB + SWZ128(row * 128 + colb));
                bf[p * 2][0] = r0;  bf[p * 2][1] = r1;
                bf[p * 2 + 1][0] = r2;  bf[p * 2 + 1][1] = r3;
            }
            #pragma unroll
            for (int i = 0; i < 4; i++)
                #pragma unroll
                for (int j = 0; j < 4; j++)
                    mma_fp16(acc[i][j], a[i], bf[j]);
        }
        __syncthreads();
    }

    // epilogue: add bias, store float2 per (row, n-pair)
    #pragma unroll
    for (int j = 0; j < 4; j++) {
        int n = n0g + wn + j * 8 + (lane & 3) * 2;
        float2 bias = __ldg((const float2*)(b_def + n));
        #pragma unroll
        for (int i = 0; i < 4; i++) {
            int m = m0g + wm + i * 16 + (lane >> 2);
            float2 v0 = make_float2(acc[i][j][0] + bias.x, acc[i][j][1] + bias.y);
            float2 v1 = make_float2(acc[i][j][2] + bias.x, acc[i][j][3] + bias.y);
            *(float2*)(out + (size_t)m * DN + n) = v0;
            *(float2*)(out + (size_t)(m + 8) * DN + n) = v1;
        }
    }
}

// =============================================================================
extern "C" void kernel_launch(void* const* d_in, const int* in_sizes, int n_in,
                              void* d_out, int out_size)
{
    const float* x     = (const float*)d_in[0];
    const float* w_off = (const float*)d_in[1];
    const float* b_off = (const float*)d_in[2];
    const float* w_def = (const float*)d_in[3];
    const float* b_def = (const float*)d_in[4];
    float* out = (float*)d_out;

    static bool attr_set = false;
    if (!attr_set) {
        cudaFuncSetAttribute(producer_kernel,
                             cudaFuncAttributeMaxDynamicSharedMemorySize,
                             SM1_TOT * (int)sizeof(float));
        cudaFuncSetAttribute(gemm_mma_kernel,
                             cudaFuncAttributeMaxDynamicSharedMemorySize, SM2_TOT);
        attr_set = true;
    }

    split_wdef_kernel<<<(DN * CKN + 255) / 256, 256>>>(w_def);
    producer_kernel<<<BN * (LOUT / TM1), NTHR1, SM1_TOT * sizeof(float)>>>(x, w_off, b_off);
    dim3 grid2(MTOT / 128, DN / 128);     // 384 x 4
    gemm_mma_kernel<<<grid2, NTHR2, SM2_TOT>>>(b_def, out);
}

// round 11
// speedup vs baseline: 12.2917x; 5.2472x over previous
#include <cuda_runtime.h>
#include <cuda_bf16.h>
#include <cuda_fp16.h>
#include <cstdint>

#define BN    32
#define LN    36864
#define CN    16
#define KN    24
#define LOUT  1536
#define DN    512
#define CKN   384
#define MTOT  (BN * LOUT)      // 49152

// single TU-wide dynamic smem symbol
extern __shared__ char smem_c[];

// ---------------- global scratch ---------------------------------------------
__device__ __half g_A [(size_t)MTOT * 384];   // sampled values, single fp16
__device__ __half g_B [(size_t)DN * 768];     // w_def  [d][hi 0:384 | lo 384:768]
__device__ __half g_Xw[(size_t)MTOT * 768];   // x windows [m][hi 0:384 | lo 384:768]
__device__ __half g_W [(size_t)48 * 768];     // w_off  [o][hi | lo]
__device__ float  g_Off[(size_t)MTOT * 48];   // predicted offsets (+bias)

// ---------------- PTX helpers ------------------------------------------------
__device__ __forceinline__ uint32_t smem_u32(const void* p) {
    return (uint32_t)__cvta_generic_to_shared(p);
}

#define SWZ128(off) ((off) ^ (((off) >> 3) & 0x70))

__device__ __forceinline__ void cp_async16(uint32_t saddr, const void* gptr) {
    asm volatile("cp.async.cg.shared.global [%0], [%1], 16;" :: "r"(saddr), "l"(gptr));
}
#define CP_COMMIT() asm volatile("cp.async.commit_group;" ::: "memory")
#define CP_WAIT(N)  asm volatile("cp.async.wait_group %0;" :: "n"(N) : "memory")

__device__ __forceinline__ void ldm_x4(uint32_t& r0, uint32_t& r1, uint32_t& r2,
                                       uint32_t& r3, uint32_t addr) {
    asm volatile("ldmatrix.sync.aligned.m8n8.x4.shared.b16 {%0,%1,%2,%3}, [%4];"
                 : "=r"(r0), "=r"(r1), "=r"(r2), "=r"(r3) : "r"(addr));
}
__device__ __forceinline__ void mma_fp16(float* d, const uint32_t* a, const uint32_t* b) {
    asm volatile(
        "mma.sync.aligned.m16n8k16.row.col.f32.f16.f16.f32 "
        "{%0,%1,%2,%3}, {%4,%5,%6,%7}, {%8,%9}, {%0,%1,%2,%3};"
        : "+f"(d[0]), "+f"(d[1]), "+f"(d[2]), "+f"(d[3])
        : "r"(a[0]), "r"(a[1]), "r"(a[2]), "r"(a[3]), "r"(b[0]), "r"(b[1]));
}

// =============================================================================
// Kernel S: split w_def -> g_B and w_off -> g_W (fp16 hi | lo)
// =============================================================================
__global__ void split_weights_kernel(const float* __restrict__ w_def,
                                     const float* __restrict__ w_off) {
    int idx = blockIdx.x * blockDim.x + threadIdx.x;
    if (idx >= (DN + 48) * CKN) return;
    int row = idx / CKN, col = idx % CKN;
    float v;
    __half* dst;
    if (row < DN) {
        v = __ldg(&w_def[(size_t)row * CKN + col]);
        dst = g_B + (size_t)row * 768;
    } else {
        v = __ldg(&w_off[(size_t)(row - DN) * CKN + col]);
        dst = g_W + (size_t)(row - DN) * 768;
    }
    __half hi = __float2half_rn(v);
    __half lo = __float2half_rn(v - __half2float(hi));
    dst[col] = hi;
    dst[384 + col] = lo;
}

// =============================================================================
// Kernel P: pack x windows -> g_Xw (fp16 hi | lo), ck = c*24+k ordering
// =============================================================================
#define TMP    32
#define NTHRP  256
// smem: s_xt [16][768] f32 = 49152 B

__global__ __launch_bounds__(NTHRP, 1)
void pack_x_kernel(const float* __restrict__ x)
{
    float* s_xt = (float*)smem_c;
    const int t    = threadIdx.x;
    const int warp = t >> 5;
    const int lane = t & 31;
    const int g = blockIdx.x;
    const int b = g / (LOUT / TMP);
    const int lout0 = (g % (LOUT / TMP)) * TMP;
    const float* xb = x + (size_t)b * LN * CN;

    // stage x window transposed [c][i], i = m*24+k (768 per c)
    {
        const float4* xw4 = (const float4*)(xb + (size_t)(lout0 * KN) * CN);
        #pragma unroll
        for (int it = 0; it < (TMP * KN * CN / 4) / NTHRP; it++) {   // 12
            int idx = t + it * NTHRP;
            float4 v = __ldg(&xw4[idx]);
            int i  = idx >> 2;
            int c4 = (idx & 3) * 4;
            s_xt[(c4 + 0) * (TMP * KN) + i] = v.x;
            s_xt[(c4 + 1) * (TMP * KN) + i] = v.y;
            s_xt[(c4 + 2) * (TMP * KN) + i] = v.z;
            s_xt[(c4 + 3) * (TMP * KN) + i] = v.w;
        }
    }
    __syncthreads();

    // write rows: [m][hi 192 u32 | lo 192 u32]
    uint32_t* gXw32 = (uint32_t*)g_Xw;
    #pragma unroll
    for (int it = 0; it < TMP / 8; it++) {               // 4
        int m = warp + 8 * it;
        size_t m_glob = (size_t)b * LOUT + lout0 + m;
        uint32_t* rowp = gXw32 + m_glob * 384;
        #pragma unroll
        for (int q = 0; q < 6; q++) {
            int col2 = lane + 32 * q;                    // 0..191
            int ck0 = col2 * 2;
            int c = ck0 / 24;
            int k0 = ck0 - c * 24;                       // even; pair stays in c
            float v0 = s_xt[c * (TMP * KN) + m * KN + k0];
            float v1 = s_xt[c * (TMP * KN) + m * KN + k0 + 1];
            __half h0 = __float2half_rn(v0);
            __half h1 = __float2half_rn(v1);
            __half l0 = __float2half_rn(v0 - __half2float(h0));
            __half l1 = __float2half_rn(v1 - __half2float(h1));
            __half2 hp = __halves2half2(h0, h1);
            __half2 lp = __halves2half2(l0, l1);
            rowp[col2]       = *(uint32_t*)&hp;
            rowp[192 + col2] = *(uint32_t*)&lp;
        }
    }
}

// =============================================================================
// Kernel O: offset GEMM  g_Off[49152][48] = g_Xw x g_W^T + b_off (3-pass split)
// CTA 128 m x 48 n, 8 warps (one m16 tile each, full N), k-chunk 64, 18 chunks.
// =============================================================================
#define NTHRO 256
#define OCHUNK 18
// smem bytes: A[2][16384] at 0, B[2][6144] at 32768
#define SOA0 0
#define SOA1 16384
#define SOB0 32768
#define SOB1 (32768 + 6144)
#define SO_TOT (32768 + 12288)      // 45056

__global__ __launch_bounds__(NTHRO, 2)
void offset_gemm_kernel(const float* __restrict__ b_off)
{
    const uint32_t sb = smem_u32(smem_c);
    const int t    = threadIdx.x;
    const int wid  = t >> 5;
    const int lane = t & 31;
    const int m0g  = blockIdx.x * 128;
    const int wm   = wid * 16;

    const int prow = t >> 3;            // 0..31
    const int pc16 = t & 7;

    float acc[6][4];
    #pragma unroll
    for (int j = 0; j < 6; j++)
        #pragma unroll
        for (int e = 0; e < 4; e++) acc[j][e] = 0.0f;

    auto prefetch = [&](int c) {
        int buf = c & 1;
        int p = c / 6, r = c % 6;
        int aOff = (p == 1 ? 384 : 0) + 64 * r;     // A: hi, lo, hi
        int bOff = (p == 2 ? 384 : 0) + 64 * r;     // W: hi, hi, lo
        uint32_t sA = sb + (buf ? SOA1 : SOA0);
        uint32_t sB = sb + (buf ? SOB1 : SOB0);
        #pragma unroll
        for (int i = 0; i < 4; i++) {
            int row = prow + i * 32;
            cp_async16(sA + SWZ128(row * 128 + pc16 * 16),
                       g_Xw + (size_t)(m0g + row) * 768 + aOff + pc16 * 8);
        }
        // B: 48 rows x 8 sixteen-byte cols = 384 loads
        {
            int idx = t;                             // 0..255
            int row = idx >> 3, c16 = idx & 7;
            cp_async16(sB + SWZ128(row * 128 + c16 * 16),
                       g_W + (size_t)row * 768 + bOff + c16 * 8);
        }
        if (t < 128) {
            int idx = t + 256;                       // 256..383
            int row = idx >> 3, c16 = idx & 7;
            cp_async16(sB + SWZ128(row * 128 + c16 * 16),
                       g_W + (size_t)row * 768 + bOff + c16 * 8);
        }
    };

    prefetch(0);
    CP_COMMIT();

    for (int c = 0; c < OCHUNK; c++) {
        if (c + 1 < OCHUNK) {
            prefetch(c + 1);
            CP_COMMIT();
            CP_WAIT(1);
        } else {
            CP_WAIT(0);
        }
        __syncthreads();

        int buf = c & 1;
        uint32_t sA = sb + (buf ? SOA1 : SOA0);
        uint32_t sB = sb + (buf ? SOB1 : SOB0);

        #pragma unroll
        for (int k16 = 0; k16 < 4; k16++) {
            int kb = k16 * 32;
            uint32_t a[4];
            {
                int row  = wm + (lane & 15);
                int colb = kb + ((lane & 16) ? 16 : 0);
                ldm_x4(a[0], a[1], a[2], a[3], sA + SWZ128(row * 128 + colb));
            }
            uint32_t bf[6][2];
            #pragma unroll
            for (int p = 0; p < 3; p++) {
                int grp  = lane >> 3;
                int nt   = p * 2 + (grp >> 1);       // 0..5
                int half = grp & 1;
                int row  = nt * 8 + (lane & 7);      // 0..47
                int colb = kb + half * 16;
                uint32_t r0, r1, r2, r3;
                ldm_x4(r0, r1, r2, r3, sB + SWZ128(row * 128 + colb));
                bf[p * 2][0] = r0;  bf[p * 2][1] = r1;
                bf[p * 2 + 1][0] = r2;  bf[p * 2 + 1][1] = r3;
            }
            #pragma unroll
            for (int j = 0; j < 6; j++)
                mma_fp16(acc[j], a, bf[j]);
        }
        __syncthreads();
    }

    // epilogue: + b_off, store float2
    #pragma unroll
    for (int j = 0; j < 6; j++) {
        int n = j * 8 + (lane & 3) * 2;
        float2 bias = __ldg((const float2*)(b_off + n));
        int m = m0g + wm + (lane >> 2);
        *(float2*)(g_Off + (size_t)m * 48 + n) =
            make_float2(acc[j][0] + bias.x, acc[j][1] + bias.y);
        *(float2*)(g_Off + (size_t)(m + 8) * 48 + n) =
            make_float2(acc[j][2] + bias.x, acc[j][3] + bias.y);
    }
}

// =============================================================================
// Kernel V: sampling — read g_Off, bilinear gather from x, write g_A (fp16)
// =============================================================================
#define TMV    32
#define NTHRV  256
#define VST    388
// smem: s_val [32][388] f32 = 49664 B
#define SMV_TOT (TMV * VST * 4)

__global__ __launch_bounds__(NTHRV, 1)
void sampling_kernel(const float* __restrict__ x)
{
    float* s_val = (float*)smem_c;
    const int t    = threadIdx.x;
    const int warp = t >> 5;
    const int lane = t & 31;
    const int g = blockIdx.x;
    const int b = g / (LOUT / TMV);
    const int lout0 = (g % (LOUT / TMV)) * TMV;
    const float* xb = x + (size_t)b * LN * CN;
    const size_t mbase = (size_t)b * LOUT + lout0;

    // bilinear sampling -> s_val[m][ck]
    #pragma unroll
    for (int it = 0; it < (TMV * KN) / NTHRV; it++) {    // 3
        int j = t + it * NTHRV;
        int m = j / KN;
        int k = j % KN;
        float2 off = __ldg((const float2*)(g_Off + (mbase + m) * 48 + 2 * k));
        float dy = off.x, dx = off.y;
        float wy = fmaxf(0.0f, 1.0f - fabsf(dy));
        int lout = lout0 + m;
        float px = (float)(lout * KN + k) + dx;
        bool valid = (px > -1.0f) && (px < (float)LN);
        float x0f = floorf(px);
        float lw = px - x0f;
        int i0 = (int)x0f;
        int i1 = i0 + 1;
        float w0 = (valid && i0 >= 0 && i0 < LN) ? (1.0f - lw) * wy : 0.0f;
        float w1 = (valid && i1 >= 0 && i1 < LN) ? lw * wy : 0.0f;
        int i0c = min(max(i0, 0), LN - 1);
        int i1c = min(max(i1, 0), LN - 1);
        const float4* p0 = (const float4*)(xb + (size_t)i0c * CN);
        const float4* p1 = (const float4*)(xb + (size_t)i1c * CN);
        float* vrow = s_val + m * VST + k;
        #pragma unroll
        for (int q = 0; q < 4; q++) {
            float4 v0 = __ldg(&p0[q]);
            float4 v1 = __ldg(&p1[q]);
            int c = q * 4;
            vrow[(c + 0) * KN] = v0.x * w0 + v1.x * w1;
            vrow[(c + 1) * KN] = v0.y * w0 + v1.y * w1;
            vrow[(c + 2) * KN] = v0.z * w0 + v1.z * w1;
            vrow[(c + 3) * KN] = v0.w * w0 + v1.w * w1;
        }
    }
    __syncthreads();

    // convert to fp16, coalesced store to g_A
    uint32_t* gA32 = (uint32_t*)g_A;
    #pragma unroll
    for (int it = 0; it < TMV / 8; it++) {               // 4
        int m = warp + 8 * it;
        uint32_t* rowp = gA32 + (mbase + m) * 192;
        const float* vrow = s_val + m * VST;
        #pragma unroll
        for (int q = 0; q < 6; q++) {
            int c2 = lane + 32 * q;
            __half2 h2 = __floats2half2_rn(vrow[2 * c2], vrow[2 * c2 + 1]);
            rowp[c2] = *(uint32_t*)&h2;
        }
    }
}

// =============================================================================
// Kernel G: main GEMM  out[49152][512] = g_A x (B_hi + B_lo)^T  (12 chunks)
// =============================================================================
#define NTHR2 256
#define NCHUNK 12
#define SM2A0 0
#define SM2B0 16384
#define SM2A1 32768
#define SM2B1 49152
#define SM2_TOT 65536

__global__ __launch_bounds__(NTHR2, 2)
void gemm_mma_kernel(const float* __restrict__ b_def, float* __restrict__ out)
{
    const uint32_t sb = smem_u32(smem_c);
    const int t    = threadIdx.x;
    const int wid  = t >> 5;
    const int lane = t & 31;
    const int m0g  = blockIdx.x * 128;
    const int n0g  = blockIdx.y * 128;

    const int wm = (wid >> 2) * 64;
    const int wn = (wid & 3) * 32;

    const int prow = t >> 3;
    const int pc16 = t & 7;

    float acc[4][4][4];
    #pragma unroll
    for (int i = 0; i < 4; i++)
        #pragma unroll
        for (int j = 0; j < 4; j++)
            #pragma unroll
            for (int e = 0; e < 4; e++) acc[i][j][e] = 0.0f;

    auto prefetch = [&](int c) {
        int buf = c & 1;
        int r = c % 6;
        int aOff = 64 * r;
        int bOff = (c / 6) * 384 + 64 * r;
        uint32_t sA = sb + (buf ? SM2A1 : SM2A0);
        uint32_t sB = sb + (buf ? SM2B1 : SM2B0);
        #pragma unroll
        for (int i = 0; i < 4; i++) {
            int row = prow + i * 32;
            cp_async16(sA + SWZ128(row * 128 + pc16 * 16),
                       g_A + (size_t)(m0g + row) * 384 + aOff + pc16 * 8);
        }
        #pragma unroll
        for (int i = 0; i < 4; i++) {
            int row = prow + i * 32;
            cp_async16(sB + SWZ128(row * 128 + pc16 * 16),
                       g_B + (size_t)(n0g + row) * 768 + bOff + pc16 * 8);
        }
    };

    prefetch(0);
    CP_COMMIT();

    for (int c = 0; c < NCHUNK; c++) {
        if (c + 1 < NCHUNK) {
            prefetch(c + 1);
            CP_COMMIT();
            CP_WAIT(1);
        } else {
            CP_WAIT(0);
        }
        __syncthreads();

        int buf = c & 1;
        uint32_t sA = sb + (buf ? SM2A1 : SM2A0);
        uint32_t sB = sb + (buf ? SM2B1 : SM2B0);

        #pragma unroll
        for (int k16 = 0; k16 < 4; k16++) {
            int kb = k16 * 32;
            uint32_t a[4][4];
            #pragma unroll
            for (int i = 0; i < 4; i++) {
                int row  = wm + i * 16 + (lane & 15);
                int colb = kb + ((lane & 16) ? 16 : 0);
                ldm_x4(a[i][0], a[i][1], a[i][2], a[i][3],
                       sA + SWZ128(row * 128 + colb));
            }
            uint32_t bf[4][2];
            #pragma unroll
            for (int p = 0; p < 2; p++) {
                int grp  = lane >> 3;
                int nt   = p * 2 + (grp >> 1);
                int half = grp & 1;
                int row  = wn + nt * 8 + (lane & 7);
                int colb = kb + half * 16;
                uint32_t r0, r1, r2, r3;
                ldm_x4(r0, r1, r2, r3, sB + SWZ128(row * 128 + colb));
                bf[p * 2][0] = r0;  bf[p * 2][1] = r1;
                bf[p * 2 + 1][0] = r2;  bf[p * 2 + 1][1] = r3;
            }
            #pragma unroll
            for (int i = 0; i < 4; i++)
                #pragma unroll
                for (int j = 0; j < 4; j++)
                    mma_fp16(acc[i][j], a[i], bf[j]);
        }
        __syncthreads();
    }

    #pragma unroll
    for (int j = 0; j < 4; j++) {
        int n = n0g + wn + j * 8 + (lane & 3) * 2;
        float2 bias = __ldg((const float2*)(b_def + n));
        #pragma unroll
        for (int i = 0; i < 4; i++) {
            int m = m0g + wm + i * 16 + (lane >> 2);
            float2 v0 = make_float2(acc[i][j][0] + bias.x, acc[i][j][1] + bias.y);
            float2 v1 = make_float2(acc[i][j][2] + bias.x, acc[i][j][3] + bias.y);
            *(float2*)(out + (size_t)m * DN + n) = v0;
            *(float2*)(out + (size_t)(m + 8) * DN + n) = v1;
        }
    }
}

// =============================================================================
extern "C" void kernel_launch(void* const* d_in, const int* in_sizes, int n_in,
                              void* d_out, int out_size)
{
    const float* x     = (const float*)d_in[0];
    const float* w_off = (const float*)d_in[1];
    const float* b_off = (const float*)d_in[2];
    const float* w_def = (const float*)d_in[3];
    const float* b_def = (const float*)d_in[4];
    float* out = (float*)d_out;

    static bool attr_set = false;
    if (!attr_set) {
        cudaFuncSetAttribute(sampling_kernel,
                             cudaFuncAttributeMaxDynamicSharedMemorySize, SMV_TOT);
        cudaFuncSetAttribute(gemm_mma_kernel,
                             cudaFuncAttributeMaxDynamicSharedMemorySize, SM2_TOT);
        attr_set = true;
    }

    split_weights_kernel<<<((DN + 48) * CKN + 255) / 256, 256>>>(w_def, w_off);
    pack_x_kernel<<<BN * (LOUT / TMP), NTHRP, 16 * TMP * KN * 4>>>(x);
    offset_gemm_kernel<<<MTOT / 128, NTHRO, SO_TOT>>>(b_off);
    sampling_kernel<<<BN * (LOUT / TMV), NTHRV, SMV_TOT>>>(x);
    dim3 grid2(MTOT / 128, DN / 128);
    gemm_mma_kernel<<<grid2, NTHR2, SM2_TOT>>>(b_def, out);
}

// round 12
// speedup vs baseline: 17.8893x; 1.4554x over previous
#include <cuda_runtime.h>
#include <cuda_bf16.h>
#include <cuda_fp16.h>
#include <cstdint>

#define BN    32
#define LN    36864
#define CN    16
#define KN    24
#define LOUT  1536
#define DN    512
#define CKN   384
#define MTOT  (BN * LOUT)      // 49152

// single TU-wide dynamic smem symbol
extern __shared__ char smem_c[];

// ---------------- global scratch (all single fp16) ---------------------------
__device__ __half g_A [(size_t)MTOT * 384];   // sampled values
__device__ __half g_B [(size_t)DN * 384];     // w_def fp16
__device__ __half g_Xw[(size_t)MTOT * 384];   // x windows fp16
__device__ __half g_W [(size_t)48 * 384];     // w_off fp16
__device__ float  g_Off[(size_t)MTOT * 48];   // predicted offsets (+bias)

// ---------------- PTX helpers ------------------------------------------------
__device__ __forceinline__ uint32_t smem_u32(const void* p) {
    return (uint32_t)__cvta_generic_to_shared(p);
}

#define SWZ128(off) ((off) ^ (((off) >> 3) & 0x70))

__device__ __forceinline__ void cp_async16(uint32_t saddr, const void* gptr) {
    asm volatile("cp.async.cg.shared.global [%0], [%1], 16;" :: "r"(saddr), "l"(gptr));
}
#define CP_COMMIT() asm volatile("cp.async.commit_group;" ::: "memory")
#define CP_WAIT(N)  asm volatile("cp.async.wait_group %0;" :: "n"(N) : "memory")

__device__ __forceinline__ void ldm_x4(uint32_t& r0, uint32_t& r1, uint32_t& r2,
                                       uint32_t& r3, uint32_t addr) {
    asm volatile("ldmatrix.sync.aligned.m8n8.x4.shared.b16 {%0,%1,%2,%3}, [%4];"
                 : "=r"(r0), "=r"(r1), "=r"(r2), "=r"(r3) : "r"(addr));
}
__device__ __forceinline__ void mma_fp16(float* d, const uint32_t* a, const uint32_t* b) {
    asm volatile(
        "mma.sync.aligned.m16n8k16.row.col.f32.f16.f16.f32 "
        "{%0,%1,%2,%3}, {%4,%5,%6,%7}, {%8,%9}, {%0,%1,%2,%3};"
        : "+f"(d[0]), "+f"(d[1]), "+f"(d[2]), "+f"(d[3])
        : "r"(a[0]), "r"(a[1]), "r"(a[2]), "r"(a[3]), "r"(b[0]), "r"(b[1]));
}

// =============================================================================
// Kernel S: convert w_def -> g_B and w_off -> g_W (single fp16)
// =============================================================================
__global__ void split_weights_kernel(const float* __restrict__ w_def,
                                     const float* __restrict__ w_off) {
    int idx = blockIdx.x * blockDim.x + threadIdx.x;
    if (idx >= (DN + 48) * CKN) return;
    if (idx < DN * CKN) {
        g_B[idx] = __float2half_rn(__ldg(&w_def[idx]));
    } else {
        int j = idx - DN * CKN;
        g_W[j] = __float2half_rn(__ldg(&w_off[j]));
    }
}

// =============================================================================
// Kernel P: pack x windows -> g_Xw (fp16), ck = c*24+k ordering
// =============================================================================
#define TMP    32
#define NTHRP  256
// smem: s_xt [16][768] f32 = 49152 B

__global__ __launch_bounds__(NTHRP, 1)
void pack_x_kernel(const float* __restrict__ x)
{
    float* s_xt = (float*)smem_c;
    const int t    = threadIdx.x;
    const int warp = t >> 5;
    const int lane = t & 31;
    const int g = blockIdx.x;
    const int b = g / (LOUT / TMP);
    const int lout0 = (g % (LOUT / TMP)) * TMP;
    const float* xb = x + (size_t)b * LN * CN;

    // stage x window transposed [c][i], i = m*24+k (768 per c)
    {
        const float4* xw4 = (const float4*)(xb + (size_t)(lout0 * KN) * CN);
        #pragma unroll
        for (int it = 0; it < (TMP * KN * CN / 4) / NTHRP; it++) {   // 12
            int idx = t + it * NTHRP;
            float4 v = __ldg(&xw4[idx]);
            int i  = idx >> 2;
            int c4 = (idx & 3) * 4;
            s_xt[(c4 + 0) * (TMP * KN) + i] = v.x;
            s_xt[(c4 + 1) * (TMP * KN) + i] = v.y;
            s_xt[(c4 + 2) * (TMP * KN) + i] = v.z;
            s_xt[(c4 + 3) * (TMP * KN) + i] = v.w;
        }
    }
    __syncthreads();

    // write rows: [m][192 u32]
    uint32_t* gXw32 = (uint32_t*)g_Xw;
    #pragma unroll
    for (int it = 0; it < TMP / 8; it++) {               // 4
        int m = warp + 8 * it;
        size_t m_glob = (size_t)b * LOUT + lout0 + m;
        uint32_t* rowp = gXw32 + m_glob * 192;
        #pragma unroll
        for (int q = 0; q < 6; q++) {
            int col2 = lane + 32 * q;                    // 0..191
            int ck0 = col2 * 2;
            int c = ck0 / 24;
            int k0 = ck0 - c * 24;                       // even; pair stays in c
            float v0 = s_xt[c * (TMP * KN) + m * KN + k0];
            float v1 = s_xt[c * (TMP * KN) + m * KN + k0 + 1];
            __half2 hp = __floats2half2_rn(v0, v1);
            rowp[col2] = *(uint32_t*)&hp;
        }
    }
}

// =============================================================================
// Kernel O: offset GEMM  g_Off[49152][48] = g_Xw x g_W^T + b_off (single fp16)
// CTA 128 m x 48 n, 8 warps (one m16 tile each, full N), k-chunk 64, 6 chunks.
// =============================================================================
#define NTHRO 256
#define OCHUNK 6
// smem bytes: A[2][16384] at 0, B[2][6144] at 32768
#define SOA0 0
#define SOA1 16384
#define SOB0 32768
#define SOB1 (32768 + 6144)
#define SO_TOT (32768 + 12288)      // 45056

__global__ __launch_bounds__(NTHRO, 2)
void offset_gemm_kernel(const float* __restrict__ b_off)
{
    const uint32_t sb = smem_u32(smem_c);
    const int t    = threadIdx.x;
    const int wid  = t >> 5;
    const int lane = t & 31;
    const int m0g  = blockIdx.x * 128;
    const int wm   = wid * 16;

    const int prow = t >> 3;            // 0..31
    const int pc16 = t & 7;

    float acc[6][4];
    #pragma unroll
    for (int j = 0; j < 6; j++)
        #pragma unroll
        for (int e = 0; e < 4; e++) acc[j][e] = 0.0f;

    auto prefetch = [&](int c) {
        int buf = c & 1;
        int kOff = 64 * c;
        uint32_t sA = sb + (buf ? SOA1 : SOA0);
        uint32_t sB = sb + (buf ? SOB1 : SOB0);
        #pragma unroll
        for (int i = 0; i < 4; i++) {
            int row = prow + i * 32;
            cp_async16(sA + SWZ128(row * 128 + pc16 * 16),
                       g_Xw + (size_t)(m0g + row) * 384 + kOff + pc16 * 8);
        }
        // B: 48 rows x 8 sixteen-byte cols = 384 loads
        {
            int idx = t;                             // 0..255
            int row = idx >> 3, c16 = idx & 7;
            cp_async16(sB + SWZ128(row * 128 + c16 * 16),
                       g_W + (size_t)row * 384 + kOff + c16 * 8);
        }
        if (t < 128) {
            int idx = t + 256;                       // 256..383
            int row = idx >> 3, c16 = idx & 7;
            cp_async16(sB + SWZ128(row * 128 + c16 * 16),
                       g_W + (size_t)row * 384 + kOff + c16 * 8);
        }
    };

    prefetch(0);
    CP_COMMIT();

    for (int c = 0; c < OCHUNK; c++) {
        if (c + 1 < OCHUNK) {
            prefetch(c + 1);
            CP_COMMIT();
            CP_WAIT(1);
        } else {
            CP_WAIT(0);
        }
        __syncthreads();

        int buf = c & 1;
        uint32_t sA = sb + (buf ? SOA1 : SOA0);
        uint32_t sB = sb + (buf ? SOB1 : SOB0);

        #pragma unroll
        for (int k16 = 0; k16 < 4; k16++) {
            int kb = k16 * 32;
            uint32_t a[4];
            {
                int row  = wm + (lane & 15);
                int colb = kb + ((lane & 16) ? 16 : 0);
                ldm_x4(a[0], a[1], a[2], a[3], sA + SWZ128(row * 128 + colb));
            }
            uint32_t bf[6][2];
            #pragma unroll
            for (int p = 0; p < 3; p++) {
                int grp  = lane >> 3;
                int nt   = p * 2 + (grp >> 1);       // 0..5
                int half = grp & 1;
                int row  = nt * 8 + (lane & 7);      // 0..47
                int colb = kb + half * 16;
                uint32_t r0, r1, r2, r3;
                ldm_x4(r0, r1, r2, r3, sB + SWZ128(row * 128 + colb));
                bf[p * 2][0] = r0;  bf[p * 2][1] = r1;
                bf[p * 2 + 1][0] = r2;  bf[p * 2 + 1][1] = r3;
            }
            #pragma unroll
            for (int j = 0; j < 6; j++)
                mma_fp16(acc[j], a, bf[j]);
        }
        __syncthreads();
    }

    // epilogue: + b_off, store float2
    #pragma unroll
    for (int j = 0; j < 6; j++) {
        int n = j * 8 + (lane & 3) * 2;
        float2 bias = __ldg((const float2*)(b_off + n));
        int m = m0g + wm + (lane >> 2);
        *(float2*)(g_Off + (size_t)m * 48 + n) =
            make_float2(acc[j][0] + bias.x, acc[j][1] + bias.y);
        *(float2*)(g_Off + (size_t)(m + 8) * 48 + n) =
            make_float2(acc[j][2] + bias.x, acc[j][3] + bias.y);
    }
}

// =============================================================================
// Kernel V: sampling — read g_Off, bilinear gather from x, write g_A (fp16)
// =============================================================================
#define TMV    32
#define NTHRV  256
#define VST    388
// smem: s_val [32][388] f32 = 49664 B
#define SMV_TOT (TMV * VST * 4)

__global__ __launch_bounds__(NTHRV, 1)
void sampling_kernel(const float* __restrict__ x)
{
    float* s_val = (float*)smem_c;
    const int t    = threadIdx.x;
    const int warp = t >> 5;
    const int lane = t & 31;
    const int g = blockIdx.x;
    const int b = g / (LOUT / TMV);
    const int lout0 = (g % (LOUT / TMV)) * TMV;
    const float* xb = x + (size_t)b * LN * CN;
    const size_t mbase = (size_t)b * LOUT + lout0;

    // bilinear sampling -> s_val[m][ck]
    #pragma unroll
    for (int it = 0; it < (TMV * KN) / NTHRV; it++) {    // 3
        int j = t + it * NTHRV;
        int m = j / KN;
        int k = j % KN;
        float2 off = __ldg((const float2*)(g_Off + (mbase + m) * 48 + 2 * k));
        float dy = off.x, dx = off.y;
        float wy = fmaxf(0.0f, 1.0f - fabsf(dy));
        int lout = lout0 + m;
        float px = (float)(lout * KN + k) + dx;
        bool valid = (px > -1.0f) && (px < (float)LN);
        float x0f = floorf(px);
        float lw = px - x0f;
        int i0 = (int)x0f;
        int i1 = i0 + 1;
        float w0 = (valid && i0 >= 0 && i0 < LN) ? (1.0f - lw) * wy : 0.0f;
        float w1 = (valid && i1 >= 0 && i1 < LN) ? lw * wy : 0.0f;
        int i0c = min(max(i0, 0), LN - 1);
        int i1c = min(max(i1, 0), LN - 1);
        const float4* p0 = (const float4*)(xb + (size_t)i0c * CN);
        const float4* p1 = (const float4*)(xb + (size_t)i1c * CN);
        float* vrow = s_val + m * VST + k;
        #pragma unroll
        for (int q = 0; q < 4; q++) {
            float4 v0 = __ldg(&p0[q]);
            float4 v1 = __ldg(&p1[q]);
            int c = q * 4;
            vrow[(c + 0) * KN] = v0.x * w0 + v1.x * w1;
            vrow[(c + 1) * KN] = v0.y * w0 + v1.y * w1;
            vrow[(c + 2) * KN] = v0.z * w0 + v1.z * w1;
            vrow[(c + 3) * KN] = v0.w * w0 + v1.w * w1;
        }
    }
    __syncthreads();

    // convert to fp16, coalesced store to g_A
    uint32_t* gA32 = (uint32_t*)g_A;
    #pragma unroll
    for (int it = 0; it < TMV / 8; it++) {               // 4
        int m = warp + 8 * it;
        uint32_t* rowp = gA32 + (mbase + m) * 192;
        const float* vrow = s_val + m * VST;
        #pragma unroll
        for (int q = 0; q < 6; q++) {
            int c2 = lane + 32 * q;
            __half2 h2 = __floats2half2_rn(vrow[2 * c2], vrow[2 * c2 + 1]);
            rowp[c2] = *(uint32_t*)&h2;
        }
    }
}

// =============================================================================
// Kernel G: main GEMM  out[49152][512] = g_A x g_B^T  (6 chunks, single fp16)
// =============================================================================
#define NTHR2 256
#define NCHUNK 6
#define SM2A0 0
#define SM2B0 16384
#define SM2A1 32768
#define SM2B1 49152
#define SM2_TOT 65536

__global__ __launch_bounds__(NTHR2, 2)
void gemm_mma_kernel(const float* __restrict__ b_def, float* __restrict__ out)
{
    const uint32_t sb = smem_u32(smem_c);
    const int t    = threadIdx.x;
    const int wid  = t >> 5;
    const int lane = t & 31;
    const int m0g  = blockIdx.x * 128;
    const int n0g  = blockIdx.y * 128;

    const int wm = (wid >> 2) * 64;
    const int wn = (wid & 3) * 32;

    const int prow = t >> 3;
    const int pc16 = t & 7;

    float acc[4][4][4];
    #pragma unroll
    for (int i = 0; i < 4; i++)
        #pragma unroll
        for (int j = 0; j < 4; j++)
            #pragma unroll
            for (int e = 0; e < 4; e++) acc[i][j][e] = 0.0f;

    auto prefetch = [&](int c) {
        int buf = c & 1;
        int kOff = 64 * c;
        uint32_t sA = sb + (buf ? SM2A1 : SM2A0);
        uint32_t sB = sb + (buf ? SM2B1 : SM2B0);
        #pragma unroll
        for (int i = 0; i < 4; i++) {
            int row = prow + i * 32;
            cp_async16(sA + SWZ128(row * 128 + pc16 * 16),
                       g_A + (size_t)(m0g + row) * 384 + kOff + pc16 * 8);
        }
        #pragma unroll
        for (int i = 0; i < 4; i++) {
            int row = prow + i * 32;
            cp_async16(sB + SWZ128(row * 128 + pc16 * 16),
                       g_B + (size_t)(n0g + row) * 384 + kOff + pc16 * 8);
        }
    };

    prefetch(0);
    CP_COMMIT();

    for (int c = 0; c < NCHUNK; c++) {
        if (c + 1 < NCHUNK) {
            prefetch(c + 1);
            CP_COMMIT();
            CP_WAIT(1);
        } else {
            CP_WAIT(0);
        }
        __syncthreads();

        int buf = c & 1;
        uint32_t sA = sb + (buf ? SM2A1 : SM2A0);
        uint32_t sB = sb + (buf ? SM2B1 : SM2B0);

        #pragma unroll
        for (int k16 = 0; k16 < 4; k16++) {
            int kb = k16 * 32;
            uint32_t a[4][4];
            #pragma unroll
            for (int i = 0; i < 4; i++) {
                int row  = wm + i * 16 + (lane & 15);
                int colb = kb + ((lane & 16) ? 16 : 0);
                ldm_x4(a[i][0], a[i][1], a[i][2], a[i][3],
                       sA + SWZ128(row * 128 + colb));
            }
            uint32_t bf[4][2];
            #pragma unroll
            for (int p = 0; p < 2; p++) {
                int grp  = lane >> 3;
                int nt   = p * 2 + (grp >> 1);
                int half = grp & 1;
                int row  = wn + nt * 8 + (lane & 7);
                int colb = kb + half * 16;
                uint32_t r0, r1, r2, r3;
                ldm_x4(r0, r1, r2, r3, sB + SWZ128(row * 128 + colb));
                bf[p * 2][0] = r0;  bf[p * 2][1] = r1;
                bf[p * 2 + 1][0] = r2;  bf[p * 2 + 1][1] = r3;
            }
            #pragma unroll
            for (int i = 0; i < 4; i++)
                #pragma unroll
                for (int j = 0; j < 4; j++)
                    mma_fp16(acc[i][j], a[i], bf[j]);
        }
        __syncthreads();
    }

    #pragma unroll
    for (int j = 0; j < 4; j++) {
        int n = n0g + wn + j * 8 + (lane & 3) * 2;
        float2 bias = __ldg((const float2*)(b_def + n));
        #pragma unroll
        for (int i = 0; i < 4; i++) {
            int m = m0g + wm + i * 16 + (lane >> 2);
            float2 v0 = make_float2(acc[i][j][0] + bias.x, acc[i][j][1] + bias.y);
            float2 v1 = make_float2(acc[i][j][2] + bias.x, acc[i][j][3] + bias.y);
            *(float2*)(out + (size_t)m * DN + n) = v0;
            *(float2*)(out + (size_t)(m + 8) * DN + n) = v1;
        }
    }
}

// =============================================================================
extern "C" void kernel_launch(void* const* d_in, const int* in_sizes, int n_in,
                              void* d_out, int out_size)
{
    const float* x     = (const float*)d_in[0];
    const float* w_off = (const float*)d_in[1];
    const float* b_off = (const float*)d_in[2];
    const float* w_def = (const float*)d_in[3];
    const float* b_def = (const float*)d_in[4];
    float* out = (float*)d_out;

    static bool attr_set = false;
    if (!attr_set) {
        cudaFuncSetAttribute(sampling_kernel,
                             cudaFuncAttributeMaxDynamicSharedMemorySize, SMV_TOT);
        cudaFuncSetAttribute(gemm_mma_kernel,
                             cudaFuncAttributeMaxDynamicSharedMemorySize, SM2_TOT);
        attr_set = true;
    }

    split_weights_kernel<<<((DN + 48) * CKN + 255) / 256, 256>>>(w_def, w_off);
    pack_x_kernel<<<BN * (LOUT / TMP), NTHRP, 16 * TMP * KN * 4>>>(x);
    offset_gemm_kernel<<<MTOT / 128, NTHRO, SO_TOT>>>(b_off);
    sampling_kernel<<<BN * (LOUT / TMV), NTHRV, SMV_TOT>>>(x);
    dim3 grid2(MTOT / 128, DN / 128);
    gemm_mma_kernel<<<grid2, NTHR2, SM2_TOT>>>(b_def, out);
}